// round 11
// baseline (speedup 1.0000x reference)
#include <cuda_runtime.h>

#define SEQ       128
#define BATCH     512
#define INPUT_DIM 128
#define HIDDEN    128
#define NQ        8

typedef unsigned long long u64;

__device__ __forceinline__ u64 pk(float lo, float hi) {
    u64 r; asm("mov.b64 %0, {%1, %2};" : "=l"(r) : "f"(lo), "f"(hi)); return r;
}
__device__ __forceinline__ void upk(u64 v, float& lo, float& hi) {
    asm("mov.b64 {%0, %1}, %2;" : "=f"(lo), "=f"(hi) : "l"(v));
}
#define FMA2(o,a,b,c) asm("fma.rn.f32x2 %0, %1, %2, %3;" : "=l"(o) : "l"(a), "l"(b), "l"(c))

// Precomputed x-part of q_in (+ bias): [SEQ*BATCH, 8]  (2MB device scratch)
__device__ float g_qx[SEQ * BATCH * NQ];

// ---------------- pre-kernel: g_qx[tb][r] = Wq[r, :128] . x[tb] + bq[r] ----------------
__global__ __launch_bounds__(128, 8)
void qx_pre(const float* __restrict__ inputs, const float* __restrict__ Wq,
            const float* __restrict__ bq)
{
    __shared__ float4 sW[8][32];   // x-part of rows 0..7
    const int tid = threadIdx.x, wid = tid >> 5, lane = tid & 31;
    const float4* Wq4 = (const float4*)Wq;
    for (int i = tid; i < 256; i += 128) sW[i >> 5][i & 31] = Wq4[(i >> 5) * 64 + (i & 31)];
    __syncthreads();

    int base = blockIdx.x * 16 + wid * 4;   // 16 (t,b) pairs per block, 4 per warp
    #pragma unroll
    for (int k = 0; k < 4; k++) {
        int tb = base + k;                  // 0..65535
        float4 xv = ((const float4*)(inputs + (size_t)tb * INPUT_DIM))[lane];
        float v0, v1, v2, v3, v4, v5, v6, v7;
        {
            float acc[8];
            #pragma unroll
            for (int r = 0; r < 8; r++) {
                float4 w = sW[r][lane];
                float a = xv.x * w.x;
                a = fmaf(xv.y, w.y, a); a = fmaf(xv.z, w.z, a); a = fmaf(xv.w, w.w, a);
                acc[r] = a;
            }
            v0 = acc[0]; v1 = acc[1]; v2 = acc[2]; v3 = acc[3];
            v4 = acc[4]; v5 = acc[5]; v6 = acc[6]; v7 = acc[7];
        }
        // 8 sums over 32 lanes in 9 shuffles; lane ends with sum of row (lane&7)
        const unsigned FM = 0xffffffffu;
        int t0 = lane & 1;
        float s0 = t0 ? v0 : v1, s1 = t0 ? v2 : v3;
        float s2 = t0 ? v4 : v5, s3 = t0 ? v6 : v7;
        float r0 = __shfl_xor_sync(FM, s0, 1);
        float r1 = __shfl_xor_sync(FM, s1, 1);
        float r2 = __shfl_xor_sync(FM, s2, 1);
        float r3 = __shfl_xor_sync(FM, s3, 1);
        float w0_ = (t0 ? v1 : v0) + r0;
        float w1_ = (t0 ? v3 : v2) + r1;
        float w2_ = (t0 ? v5 : v4) + r2;
        float w3_ = (t0 ? v7 : v6) + r3;
        int t1 = (lane >> 1) & 1;
        float s4 = t1 ? w0_ : w1_, s5 = t1 ? w2_ : w3_;
        float r4 = __shfl_xor_sync(FM, s4, 2);
        float r5 = __shfl_xor_sync(FM, s5, 2);
        float x0_ = (t1 ? w1_ : w0_) + r4;
        float x1_ = (t1 ? w3_ : w2_) + r5;
        int t2 = (lane >> 2) & 1;
        float s6 = t2 ? x0_ : x1_;
        float r6 = __shfl_xor_sync(FM, s6, 4);
        float y = (t2 ? x1_ : x0_) + r6;
        y += __shfl_xor_sync(FM, y, 8);
        y += __shfl_xor_sync(FM, y, 16);
        if (lane < 8) g_qx[tb * NQ + lane] = y + bq[lane];
    }
}

// ---------------- recurrent kernel ----------------
__global__ __launch_bounds__(128, 4)
void qlstm_all(const float* __restrict__ Wq,
               const float* __restrict__ pf,
               const float* __restrict__ pi_,
               const float* __restrict__ pg,
               const float* __restrict__ po,
               const float* __restrict__ Wf, const float* __restrict__ bf,
               const float* __restrict__ Wi, const float* __restrict__ bi,
               const float* __restrict__ Wg, const float* __restrict__ bg,
               const float* __restrict__ Wo, const float* __restrict__ bo,
               float* __restrict__ out)
{
    const int b    = blockIdx.x;
    const int tid  = threadIdx.x;
    const int wid  = tid >> 5;
    const int lane = tid & 31;

    __shared__ float4 sWqH[8][32];          // 4KB: Wq rows 0..7, h-part (cols 128..255)
    __shared__ float4 sWg4[NQ][HIDDEN];     // 16KB: raw (Wf,Wi,Wg,Wo) per (wire,hidden)
    __shared__ float  sH[2][HIDDEN];        // h, double-buffered (read as float4)
    __shared__ float2 sCS[2][8];            // (cos th, sin th) FULL angle per wire
    __shared__ __align__(16) float zarr[2][NQ][4];  // per wire: (zf,zi,zg,zo)

    // per-warp circuit constants (FULL angles), registers
    float Cg[NQ], Sg[NQ], cg[NQ], sg[NQ];
    {
        const float4* Wq4 = (const float4*)Wq;
        for (int i = tid; i < 256; i += 128)
            sWqH[i >> 5][i & 31] = Wq4[(i >> 5) * 64 + 32 + (i & 31)];
        for (int i = tid; i < HIDDEN * NQ; i += 128) {
            int h = i >> 3, w = i & 7;
            sWg4[w][h] = make_float4(Wf[i], Wi[i], Wg[i], Wo[i]);
        }
        const float* prm = (wid == 0) ? pf : (wid == 1) ? pi_ : (wid == 2) ? pg : po;
        #pragma unroll
        for (int w = 0; w < NQ; w++) {
            __sincosf(prm[w],      &Sg[w], &Cg[w]);   // d0 layer
            __sincosf(prm[NQ + w], &sg[w], &cg[w]);   // d1 layer
        }
        sH[0][tid] = 0.f;
    }

    const float bfr = bf[tid], bir = bi[tid], bgr = bg[tid], bor = bo[tid];
    float creg = 0.f;
    const int v = lane & 7;                 // this lane's output wire

    // prefetch qx for t=0 (lanes 0,1 own rows 2wid, 2wid+1)
    float qxc = 0.f;
    if (lane < 2) qxc = g_qx[(size_t)b * NQ + 2 * wid + lane];
    __syncthreads();

    for (int t = 0; t < SEQ; t++) {
        const int buf = t & 1;
        __syncthreads();   // A: h (and zarr reuse) visible

        // prefetch next qx (h-independent, off critical path)
        float qxn = 0.f;
        if (t + 1 < SEQ && lane < 2)
            qxn = g_qx[((size_t)(t + 1) * BATCH + b) * NQ + 2 * wid + lane];

        // ---- q_in h-part GEMM: warp wid -> rows 2wid, 2wid+1 ----
        {
            float4 hv = ((const float4*)sH[buf])[lane];
            float4 wa = sWqH[2 * wid][lane];
            float4 wc = sWqH[2 * wid + 1][lane];
            float a0 = hv.x * wa.x;
            a0 = fmaf(hv.y, wa.y, a0); a0 = fmaf(hv.z, wa.z, a0); a0 = fmaf(hv.w, wa.w, a0);
            float a1 = hv.x * wc.x;
            a1 = fmaf(hv.y, wc.y, a1); a1 = fmaf(hv.z, wc.z, a1); a1 = fmaf(hv.w, wc.w, a1);
            const unsigned FM = 0xffffffffu;
            int t0 = lane & 1;
            float s  = t0 ? a0 : a1;
            float rr = __shfl_xor_sync(FM, s, 1);
            float vsum = (t0 ? a1 : a0) + rr;
            #pragma unroll
            for (int o = 2; o <= 16; o <<= 1) vsum += __shfl_xor_sync(FM, vsum, o);
            if (lane < 2) {
                float qv = vsum + qxc;
                float sq, cq;
                __sincosf(qv, &sq, &cq);             // FULL angle
                sCS[buf][2 * wid + lane] = make_float2(cq, sq);
            }
        }
        __syncthreads();   // B: sCS visible

        // ---- Heisenberg DP (REAL 4-state): a=W00r, bb=W10r, c=W01r, d=W11i ----
        float a = 1.f, bb = 0.f, c = 0.f, d = 0.f;
        #pragma unroll
        for (int j = 7; j >= 0; j--) {
            float zf, xf, yf;
            if (j == 7) { zf = 0.f; xf = 1.f; yf = 0.f; }   // virtual wire 8
            else {
                float2 cs = sCS[buf][j + 1];
                zf = Cg[j + 1] * cs.x;
                xf = Sg[j + 1] * cs.x;
                yf = -cs.y;
            }
            if (j <= v) {
                float cj = cg[j], sj = sg[j];
                float na = cj * fmaf(yf, d, bb * zf);
                float nb = cj * fmaf(xf, c, a);
                float nc = -sj * fmaf(xf, a, c);
                float nd = -sj * fmaf(-yf, bb, d * zf);
                a = na; bb = nb; c = nc; d = nd;
            }
        }
        {
            float2 cs0 = sCS[buf][0];
            float E = a;
            E = fmaf(Sg[0] * cs0.x, c, E);
            E = fmaf(Cg[0] * cs0.x, bb, E);
            E = fmaf(-cs0.y, d, E);
            if (lane < 8) zarr[buf][lane][wid] = E;   // wire = lane, gate = wid
        }
        __syncthreads();   // C: zarr visible

        // ---- gate projections (f32x2 pairs) + LSTM update ----
        {
            u64 accfi = pk(bfr, bir);
            u64 accgo = pk(bgr, bor);
            #pragma unroll
            for (int w = 0; w < NQ; w++) {
                float4 zz = *(const float4*)&zarr[buf][w][0];
                float4 ww = sWg4[w][tid];
                u64 zfi = pk(zz.x, zz.y), zgo = pk(zz.z, zz.w);
                u64 wfi = pk(ww.x, ww.y), wgo = pk(ww.z, ww.w);
                FMA2(accfi, zfi, wfi, accfi);
                FMA2(accgo, zgo, wgo, accgo);
            }
            float accf, acci, accg, acco;
            upk(accfi, accf, acci);
            upk(accgo, accg, acco);

            float fg = __fdividef(1.f, 1.f + __expf(-accf));
            float ig = __fdividef(1.f, 1.f + __expf(-acci));
            float e2 = __expf(2.f * accg);
            float gg = __fdividef(e2 - 1.f, e2 + 1.f);
            float og = __fdividef(1.f, 1.f + __expf(-acco));

            creg = fmaf(fg, creg, ig * gg);
            float e2c = __expf(2.f * creg);
            float hnew = og * __fdividef(e2c - 1.f, e2c + 1.f);

            sH[buf ^ 1][tid] = hnew;   // h for next step (safe: barrier A before read)
            out[(size_t)t * BATCH * HIDDEN + (size_t)b * HIDDEN + tid] = hnew;
        }
        qxc = qxn;
    }

    // ---- final hx, cx ----
    size_t base = (size_t)SEQ * BATCH * HIDDEN;
    out[base + (size_t)b * HIDDEN + tid] = sH[SEQ & 1][tid];
    out[base + (size_t)BATCH * HIDDEN + (size_t)b * HIDDEN + tid] = creg;
}

extern "C" void kernel_launch(void* const* d_in, const int* in_sizes, int n_in,
                              void* d_out, int out_size)
{
    const float* inputs = (const float*)d_in[0];
    const float* Wq     = (const float*)d_in[1];
    const float* bq     = (const float*)d_in[2];
    const float* pf     = (const float*)d_in[3];
    const float* pi_    = (const float*)d_in[4];
    const float* pg     = (const float*)d_in[5];
    const float* po     = (const float*)d_in[6];
    const float* Wf     = (const float*)d_in[7];
    const float* bf     = (const float*)d_in[8];
    const float* Wi     = (const float*)d_in[9];
    const float* bi     = (const float*)d_in[10];
    const float* Wg     = (const float*)d_in[11];
    const float* bg     = (const float*)d_in[12];
    const float* Wo     = (const float*)d_in[13];
    const float* bo     = (const float*)d_in[14];
    float* out = (float*)d_out;

    qx_pre<<<4096, 128>>>(inputs, Wq, bq);
    qlstm_all<<<BATCH, 128>>>(Wq, pf, pi_, pg, po,
                              Wf, bf, Wi, bi, Wg, bg, Wo, bo, out);
}

// round 12
// speedup vs baseline: 1.2688x; 1.2688x over previous
#include <cuda_runtime.h>

#define SEQ       128
#define BATCH     512
#define INPUT_DIM 128
#define HIDDEN    128
#define NQ        8

typedef unsigned long long u64;

__device__ __forceinline__ u64 pk(float lo, float hi) {
    u64 r; asm("mov.b64 %0, {%1, %2};" : "=l"(r) : "f"(lo), "f"(hi)); return r;
}
__device__ __forceinline__ void upk(u64 v, float& lo, float& hi) {
    asm("mov.b64 {%0, %1}, %2;" : "=f"(lo), "=f"(hi) : "l"(v));
}
#define FMA2(o,a,b,c) asm("fma.rn.f32x2 %0, %1, %2, %3;" : "=l"(o) : "l"(a), "l"(b), "l"(c))

// Precomputed x-part of q_in (+ bias): [SEQ*BATCH, 8]  (2MB device scratch)
__device__ float g_qx[SEQ * BATCH * NQ];

// ---------------- pre-kernel: g_qx[tb][r] = Wq[r, :128] . x[tb] + bq[r] ----------------
__global__ __launch_bounds__(128, 8)
void qx_pre(const float* __restrict__ inputs, const float* __restrict__ Wq,
            const float* __restrict__ bq)
{
    __shared__ float4 sW[8][32];   // x-part of rows 0..7
    const int tid = threadIdx.x, wid = tid >> 5, lane = tid & 31;
    const float4* Wq4 = (const float4*)Wq;
    for (int i = tid; i < 256; i += 128) sW[i >> 5][i & 31] = Wq4[(i >> 5) * 64 + (i & 31)];
    __syncthreads();

    int base = blockIdx.x * 16 + wid * 4;
    #pragma unroll
    for (int k = 0; k < 4; k++) {
        int tb = base + k;
        float4 xv = ((const float4*)(inputs + (size_t)tb * INPUT_DIM))[lane];
        float acc[8];
        #pragma unroll
        for (int r = 0; r < 8; r++) {
            float4 w = sW[r][lane];
            float a = xv.x * w.x;
            a = fmaf(xv.y, w.y, a); a = fmaf(xv.z, w.z, a); a = fmaf(xv.w, w.w, a);
            acc[r] = a;
        }
        const unsigned FM = 0xffffffffu;
        int t0 = lane & 1;
        float s0 = t0 ? acc[0] : acc[1], s1 = t0 ? acc[2] : acc[3];
        float s2 = t0 ? acc[4] : acc[5], s3 = t0 ? acc[6] : acc[7];
        float r0 = __shfl_xor_sync(FM, s0, 1);
        float r1 = __shfl_xor_sync(FM, s1, 1);
        float r2 = __shfl_xor_sync(FM, s2, 1);
        float r3 = __shfl_xor_sync(FM, s3, 1);
        float w0_ = (t0 ? acc[1] : acc[0]) + r0;
        float w1_ = (t0 ? acc[3] : acc[2]) + r1;
        float w2_ = (t0 ? acc[5] : acc[4]) + r2;
        float w3_ = (t0 ? acc[7] : acc[6]) + r3;
        int t1 = (lane >> 1) & 1;
        float s4 = t1 ? w0_ : w1_, s5 = t1 ? w2_ : w3_;
        float r4 = __shfl_xor_sync(FM, s4, 2);
        float r5 = __shfl_xor_sync(FM, s5, 2);
        float x0_ = (t1 ? w1_ : w0_) + r4;
        float x1_ = (t1 ? w3_ : w2_) + r5;
        int t2 = (lane >> 2) & 1;
        float s6 = t2 ? x0_ : x1_;
        float r6 = __shfl_xor_sync(FM, s6, 4);
        float y = (t2 ? x1_ : x0_) + r6;
        y += __shfl_xor_sync(FM, y, 8);
        y += __shfl_xor_sync(FM, y, 16);
        if (lane < 8) g_qx[tb * NQ + lane] = y + bq[lane];
    }
}

// ---------------- recurrent kernel: ONE WARP per batch element ----------------
__global__ __launch_bounds__(32)
void qlstm_all(const float* __restrict__ Wq,
               const float* __restrict__ pf,
               const float* __restrict__ pi_,
               const float* __restrict__ pg,
               const float* __restrict__ po,
               const float* __restrict__ Wf, const float* __restrict__ bf,
               const float* __restrict__ Wi, const float* __restrict__ bi,
               const float* __restrict__ Wg, const float* __restrict__ bg,
               const float* __restrict__ Wo, const float* __restrict__ bo,
               float* __restrict__ out)
{
    const int b    = blockIdx.x;
    const int lane = threadIdx.x;
    const int g    = lane >> 3;      // gate 0..3 (f,i,g,o)
    const int v    = lane & 7;       // output wire for the DP
    const unsigned FM = 0xffffffffu;

    __shared__ float4 sWqH[8][32];              // 4KB : Wq rows 0..7, h-part
    __shared__ float4 sWg4[NQ][HIDDEN];         // 16KB: (Wf,Wi,Wg,Wo) per (wire,hidden)
    __shared__ float  sH[HIDDEN];               // current h
    __shared__ __align__(16) float zsm[NQ][4];  // [wire][gate]

    // ---- per-lane circuit constants (this lane's gate), FULL angles ----
    float Cg[NQ], Sg[NQ], cg[NQ], sg[NQ];
    {
        const float* prm = (g == 0) ? pf : (g == 1) ? pi_ : (g == 2) ? pg : po;
        #pragma unroll
        for (int w = 0; w < NQ; w++) {
            __sincosf(prm[w],      &Sg[w], &Cg[w]);   // d0 layer
            __sincosf(prm[NQ + w], &sg[w], &cg[w]);   // d1 layer
        }
    }
    // ---- weights to smem (one warp) ----
    {
        const float4* Wq4 = (const float4*)Wq;
        #pragma unroll
        for (int k = 0; k < 8; k++)
            sWqH[k][lane] = Wq4[k * 64 + 32 + lane];
        #pragma unroll
        for (int k = 0; k < 4; k++) {
            int h = k * 32 + lane;
            float4 f0 = ((const float4*)(Wf + h * NQ))[0], f1 = ((const float4*)(Wf + h * NQ))[1];
            float4 i0 = ((const float4*)(Wi + h * NQ))[0], i1 = ((const float4*)(Wi + h * NQ))[1];
            float4 g0 = ((const float4*)(Wg + h * NQ))[0], g1 = ((const float4*)(Wg + h * NQ))[1];
            float4 o0 = ((const float4*)(Wo + h * NQ))[0], o1 = ((const float4*)(Wo + h * NQ))[1];
            sWg4[0][h] = make_float4(f0.x, i0.x, g0.x, o0.x);
            sWg4[1][h] = make_float4(f0.y, i0.y, g0.y, o0.y);
            sWg4[2][h] = make_float4(f0.z, i0.z, g0.z, o0.z);
            sWg4[3][h] = make_float4(f0.w, i0.w, g0.w, o0.w);
            sWg4[4][h] = make_float4(f1.x, i1.x, g1.x, o1.x);
            sWg4[5][h] = make_float4(f1.y, i1.y, g1.y, o1.y);
            sWg4[6][h] = make_float4(f1.z, i1.z, g1.z, o1.z);
            sWg4[7][h] = make_float4(f1.w, i1.w, g1.w, o1.w);
        }
        ((float4*)sH)[lane] = make_float4(0.f, 0.f, 0.f, 0.f);
    }
    // per-lane biases for its 4 hidden units h = u*32+lane
    float bfv[4], biv[4], bgv[4], bov[4], cv[4];
    #pragma unroll
    for (int u = 0; u < 4; u++) {
        int h = u * 32 + lane;
        bfv[u] = bf[h]; biv[u] = bi[h]; bgv[u] = bg[h]; bov[u] = bo[h];
        cv[u] = 0.f;
    }

    float qxc = g_qx[(size_t)b * NQ + v];    // t=0, row v
    float hn[4];
    __syncwarp();

    for (int t = 0; t < SEQ; t++) {
        // ---- h-part GEMM: 8 rows, 9-shfl multi-reduce ----
        float4 hv = ((const float4*)sH)[lane];
        float acc[8];
        #pragma unroll
        for (int r = 0; r < 8; r++) {
            float4 w = sWqH[r][lane];
            float a = hv.x * w.x;
            a = fmaf(hv.y, w.y, a); a = fmaf(hv.z, w.z, a); a = fmaf(hv.w, w.w, a);
            acc[r] = a;
        }
        float y;
        {
            int t0 = lane & 1;
            float s0 = t0 ? acc[0] : acc[1], s1 = t0 ? acc[2] : acc[3];
            float s2 = t0 ? acc[4] : acc[5], s3 = t0 ? acc[6] : acc[7];
            float r0 = __shfl_xor_sync(FM, s0, 1);
            float r1 = __shfl_xor_sync(FM, s1, 1);
            float r2 = __shfl_xor_sync(FM, s2, 1);
            float r3 = __shfl_xor_sync(FM, s3, 1);
            float w0_ = (t0 ? acc[1] : acc[0]) + r0;
            float w1_ = (t0 ? acc[3] : acc[2]) + r1;
            float w2_ = (t0 ? acc[5] : acc[4]) + r2;
            float w3_ = (t0 ? acc[7] : acc[6]) + r3;
            int t1 = (lane >> 1) & 1;
            float s4 = t1 ? w0_ : w1_, s5 = t1 ? w2_ : w3_;
            float r4 = __shfl_xor_sync(FM, s4, 2);
            float r5 = __shfl_xor_sync(FM, s5, 2);
            float x0_ = (t1 ? w1_ : w0_) + r4;
            float x1_ = (t1 ? w3_ : w2_) + r5;
            int t2 = (lane >> 2) & 1;
            float s6 = t2 ? x0_ : x1_;
            float r6 = __shfl_xor_sync(FM, s6, 4);
            y = (t2 ? x1_ : x0_) + r6;       // row (lane&7) partial
            y += __shfl_xor_sync(FM, y, 8);
            y += __shfl_xor_sync(FM, y, 16); // row (lane&7) total, ALL lanes
        }
        // prefetch next qx (h-independent)
        float qxn = 0.f;
        if (t + 1 < SEQ) qxn = g_qx[((size_t)(t + 1) * BATCH + b) * NQ + v];

        // every lane: sincos of ITS row (wire v) — cs[j] lives in lane j (j<8)
        float sq, cq;
        __sincosf(y + qxc, &sq, &cq);

        // ---- Heisenberg DP (real 4-state), lane computes z[g][v] ----
        float a_ = 1.f, bb = 0.f, c_ = 0.f, d_ = 0.f;
        #pragma unroll
        for (int j = 7; j >= 0; j--) {
            float zf, xf, yf;
            if (j == 7) { zf = 0.f; xf = 1.f; yf = 0.f; }
            else {
                float cqj = __shfl_sync(FM, cq, j + 1);
                float sqj = __shfl_sync(FM, sq, j + 1);
                zf = Cg[j + 1] * cqj;
                xf = Sg[j + 1] * cqj;
                yf = -sqj;
            }
            if (j <= v) {
                float cj = cg[j], sj = sg[j];
                float na = cj * fmaf(yf, d_, bb * zf);
                float nb = cj * fmaf(xf, c_, a_);
                float nc = -sj * fmaf(xf, a_, c_);
                float nd = -sj * fmaf(-yf, bb, d_ * zf);
                a_ = na; bb = nb; c_ = nc; d_ = nd;
            }
        }
        {
            float cq0 = __shfl_sync(FM, cq, 0);
            float sq0 = __shfl_sync(FM, sq, 0);
            float E = a_;
            E = fmaf(Sg[0] * cq0, c_, E);
            E = fmaf(Cg[0] * cq0, bb, E);
            E = fmaf(-sq0, d_, E);
            zsm[v][g] = E;
        }
        __syncwarp();

        // ---- epilogue: 4 hidden units per lane ----
        float4 zw[8];
        #pragma unroll
        for (int w = 0; w < NQ; w++) zw[w] = *(const float4*)&zsm[w][0];

        #pragma unroll
        for (int u = 0; u < 4; u++) {
            int h = u * 32 + lane;
            u64 accfi = pk(bfv[u], biv[u]);
            u64 accgo = pk(bgv[u], bov[u]);
            #pragma unroll
            for (int w = 0; w < NQ; w++) {
                float4 ww = sWg4[w][h];
                FMA2(accfi, pk(zw[w].x, zw[w].y), pk(ww.x, ww.y), accfi);
                FMA2(accgo, pk(zw[w].z, zw[w].w), pk(ww.z, ww.w), accgo);
            }
            float accf, acci, accg, acco;
            upk(accfi, accf, acci);
            upk(accgo, accg, acco);

            float fg = __fdividef(1.f, 1.f + __expf(-accf));
            float ig = __fdividef(1.f, 1.f + __expf(-acci));
            float e2 = __expf(2.f * accg);
            float gg = __fdividef(e2 - 1.f, e2 + 1.f);
            float og = __fdividef(1.f, 1.f + __expf(-acco));

            cv[u] = fmaf(fg, cv[u], ig * gg);
            float e2c = __expf(2.f * cv[u]);
            hn[u] = og * __fdividef(e2c - 1.f, e2c + 1.f);
        }
        __syncwarp();   // all lanes done reading sH/zsm
        float* outp = out + (size_t)t * BATCH * HIDDEN + (size_t)b * HIDDEN;
        #pragma unroll
        for (int u = 0; u < 4; u++) {
            sH[u * 32 + lane] = hn[u];
            outp[u * 32 + lane] = hn[u];
        }
        __syncwarp();   // h visible before next step's read
        qxc = qxn;
    }

    // ---- final hx, cx ----
    size_t base = (size_t)SEQ * BATCH * HIDDEN;
    #pragma unroll
    for (int u = 0; u < 4; u++) {
        out[base + (size_t)b * HIDDEN + u * 32 + lane] = hn[u];
        out[base + (size_t)BATCH * HIDDEN + (size_t)b * HIDDEN + u * 32 + lane] = cv[u];
    }
}

extern "C" void kernel_launch(void* const* d_in, const int* in_sizes, int n_in,
                              void* d_out, int out_size)
{
    const float* inputs = (const float*)d_in[0];
    const float* Wq     = (const float*)d_in[1];
    const float* bq     = (const float*)d_in[2];
    const float* pf     = (const float*)d_in[3];
    const float* pi_    = (const float*)d_in[4];
    const float* pg     = (const float*)d_in[5];
    const float* po     = (const float*)d_in[6];
    const float* Wf     = (const float*)d_in[7];
    const float* bf     = (const float*)d_in[8];
    const float* Wi     = (const float*)d_in[9];
    const float* bi     = (const float*)d_in[10];
    const float* Wg     = (const float*)d_in[11];
    const float* bg     = (const float*)d_in[12];
    const float* Wo     = (const float*)d_in[13];
    const float* bo     = (const float*)d_in[14];
    float* out = (float*)d_out;

    qx_pre<<<4096, 128>>>(inputs, Wq, bq);
    qlstm_all<<<BATCH, 32>>>(Wq, pf, pi_, pg, po,
                             Wf, bf, Wi, bi, Wg, bg, Wo, bo, out);
}